// round 4
// baseline (speedup 1.0000x reference)
#include <cuda_runtime.h>
#include <cuda_fp16.h>
#include <math.h>

// ---------------------------------------------------------------------------
// ClassCapsule routing, B=64, IN_CAPS=2048, IN_DIM=16, N_CAPS=64, CAP_DIM=16
//
// Key algebra: routing logits are linear in agreements:
//   b1 = u.v0 ;  b2 = u.v0 + u.v1 = u.(v0+v1)
// so no per-(b,i,n) logit buffer is needed — each route pass dots u against a
// running vlogit (v0, then v0+v1). Both passes are the SAME kernel.
//
// u_hat stored fp16 (halves streaming); all reductions fp32.
// Projection uses packed fma.rn.f32x2 (2 FMAs per issue slot).
// No global atomics anywhere: route/reduce0 write per-(b,chunk) partials,
// squash sums the 8 partials. Fully deterministic across graph replays.
//
// Route lane map (16B loads): chunk q' in 0..3, lane l in 0..31 owns the
// uint4 (8 halfs) at j = 256q' + 8l  ->  n = 16q' + (l>>1), d = 8(l&1)..+7.
// Dot over d completes with ONE shfl_xor(1); softmax over n reduces over q'
// locally then shfl_xor 2,4,8,16.
//
// Pipeline:
//   proj -> reduce0 (c=1/64 partials) -> squash<0> (v0; vlogit=v0)
//   -> route (logits=u.vlogit; partials s1) -> squash<1> (v1; vlogit+=v1)
//   -> route (partials s2) -> squash<2> (v2 -> d_out)
// ---------------------------------------------------------------------------

#define B_      64
#define ICAPS   2048
#define IDIM    16
#define NCAPS   64
#define CDIM    16
#define J       (NCAPS*CDIM)              // 1024
#define NCH     8                         // i-chunks (partial buffers)
#define UHAT_B_STRIDE ((size_t)ICAPS*J)   // 2,097,152 elements per batch

static __device__ __half g_uhat[(size_t)B_*ICAPS*J];   // 268 MB scratch
static __device__ float  g_spart[B_*NCH*J];            // 2 MB partial sums
static __device__ float  g_vlogit[B_*J];               // v0, then v0+v1

typedef unsigned long long ull;

__device__ __forceinline__ ull pack2(float a, float b) {
    ull r; asm("mov.b64 %0, {%1, %2};" : "=l"(r) : "f"(a), "f"(b)); return r;
}
__device__ __forceinline__ void unpack2(ull v, float& a, float& b) {
    asm("mov.b64 {%0, %1}, %2;" : "=f"(a), "=f"(b) : "l"(v));
}
__device__ __forceinline__ ull fma2(ull a, ull b, ull c) {
    ull d; asm("fma.rn.f32x2 %0, %1, %2, %3;" : "=l"(d) : "l"(a), "l"(b), "l"(c));
    return d;
}

// ---------------------------------------------------------------------------
// Projection: one block per input capsule i. Thread t owns j = 4t..4t+3.
// W columns in registers as f32x2 pairs; x broadcast from SMEM as duplicated
// f32x2 pairs. Inner loop: 16 x LDS.64 + 32 x fma.rn.f32x2 per batch element.
__global__ __launch_bounds__(256) void proj_kernel(
    const float* __restrict__ x, const float* __restrict__ W)
{
    int i = blockIdx.x;
    int t = threadIdx.x;
    __shared__ ull xs2[B_ * IDIM];   // xs2[b*16+k] = {x, x}

    #pragma unroll
    for (int r = 0; r < 4; r++) {
        int idx = t + r * 256;
        int b = idx >> 4, k = idx & 15;
        float xv = x[(size_t)b * (ICAPS * IDIM) + i * IDIM + k];
        xs2[idx] = pack2(xv, xv);
    }
    __syncthreads();

    const float4* Wi = (const float4*)(W + (size_t)i * (IDIM * J));
    ull w01[16], w23[16];
    #pragma unroll
    for (int k = 0; k < 16; k++) {
        float4 wv = Wi[k * (J / 4) + t];
        w01[k] = pack2(wv.x, wv.y);
        w23[k] = pack2(wv.z, wv.w);
    }

    __half* outp = g_uhat + (size_t)i * J + 4 * t;
    for (int b = 0; b < B_; b++) {
        ull a01 = 0ULL, a23 = 0ULL;   // {0.f, 0.f}
        #pragma unroll
        for (int k = 0; k < 16; k++) {
            ull xk = xs2[b * 16 + k];
            a01 = fma2(xk, w01[k], a01);
            a23 = fma2(xk, w23[k], a23);
        }
        float f0, f1, f2, f3;
        unpack2(a01, f0, f1);
        unpack2(a23, f2, f3);
        __half2 h0 = __floats2half2_rn(f0, f1);
        __half2 h1 = __floats2half2_rn(f2, f3);
        uint2 st;
        st.x = *reinterpret_cast<unsigned*>(&h0);
        st.y = *reinterpret_cast<unsigned*>(&h1);
        *reinterpret_cast<uint2*>(outp + (size_t)b * UHAT_B_STRIDE) = st;
    }
}

// ---------------------------------------------------------------------------
// Iteration 0 weighted sum: c = 1/64 exactly (softmax of zeros).
// grid (64, 8): block (b, chunk of 256 i). Writes partial to g_spart[b][ch].
__global__ __launch_bounds__(256) void reduce0_kernel()
{
    int b = blockIdx.x, ch = blockIdx.y;
    int t = threadIdx.x;
    float a0 = 0.f, a1 = 0.f, a2 = 0.f, a3 = 0.f;
    const __half* base = g_uhat + (size_t)b * UHAT_B_STRIDE
                       + (size_t)ch * 256 * J + 4 * t;
    #pragma unroll 8
    for (int i = 0; i < 256; i++) {
        uint2 r = *reinterpret_cast<const uint2*>(base + (size_t)i * J);
        __half2 h0 = *reinterpret_cast<__half2*>(&r.x);
        __half2 h1 = *reinterpret_cast<__half2*>(&r.y);
        float2 f0 = __half22float2(h0);
        float2 f1 = __half22float2(h1);
        a0 += f0.x; a1 += f0.y; a2 += f1.x; a3 += f1.y;
    }
    const float sc = 1.0f / 64.0f;
    float4 outv = make_float4(a0 * sc, a1 * sc, a2 * sc, a3 * sc);
    *(float4*)&g_spart[(b * NCH + ch) * J + 4 * t] = outv;
}

// ---------------------------------------------------------------------------
// squash: s = sum_ch spart + bias ; v = s * sqrt(ss+EPS)/(1+ss+EPS).
// 16 lanes per (b,n) capsule. MODE 0: vlogit = v. MODE 1: vlogit += v.
// MODE 2: write v to d_out.
template <int MODE>
__global__ __launch_bounds__(256) void squash_kernel(
    const float* __restrict__ bias, float* __restrict__ out)
{
    int idx = blockIdx.x * 256 + threadIdx.x;       // b*1024 + n*16 + d
    int b = idx >> 10, j = idx & (J - 1);
    float sv = bias[j];
    #pragma unroll
    for (int ch = 0; ch < NCH; ch++)
        sv += g_spart[(b * NCH + ch) * J + j];
    float sq = sv * sv;
    #pragma unroll
    for (int o = 1; o < 16; o <<= 1)
        sq += __shfl_xor_sync(0xffffffffu, sq, o);
    float tt = sq + 1e-7f;
    float nn = sqrtf(tt);
    float v  = sv * (nn / (1.0f + tt));
    if (MODE == 0) g_vlogit[idx] = v;
    else if (MODE == 1) g_vlogit[idx] += v;
    else out[idx] = v;
}

// ---------------------------------------------------------------------------
// Fused routing pass: per (b,i) tile (1024 halfs, read ONCE via 4 LDG.128):
//   t[n] = sum_d u * vlogit ; c = softmax_n(t) ; s += c*u
// (register partials -> SMEM block reduce -> g_spart[b][ch], plain stores).
// Lane map: q' in 0..3, lane l: 8 halfs at j=256q'+8l
//   -> n = 16q' + (l>>1), d = 8(l&1)..+7.
__global__ __launch_bounds__(256, 2) void route_kernel()
{
    int b = blockIdx.x, ch = blockIdx.y;            // grid (64, 8)
    int w = threadIdx.x >> 5, l = threadIdx.x & 31;

    // vlogit for this lane's 8 j's per chunk; sacc mirrors it.
    float4 vqa[4], vqb[4], sacca[4], saccb[4];
    #pragma unroll
    for (int q = 0; q < 4; q++) {
        vqa[q] = *(const float4*)&g_vlogit[b * J + q * 256 + l * 8];
        vqb[q] = *(const float4*)&g_vlogit[b * J + q * 256 + l * 8 + 4];
        sacca[q] = make_float4(0.f, 0.f, 0.f, 0.f);
        saccb[q] = make_float4(0.f, 0.f, 0.f, 0.f);
    }

    int i0 = ch * 256 + w * 32;
    #pragma unroll 2
    for (int ii = 0; ii < 32; ii++) {
        int i = i0 + ii;
        const __half* up = g_uhat + (size_t)b * UHAT_B_STRIDE + (size_t)i * J;
        float4 ua[4], ub[4];
        #pragma unroll
        for (int q = 0; q < 4; q++) {
            uint4 r = *reinterpret_cast<const uint4*>(up + q * 256 + 8 * l);
            float2 f0 = __half22float2(*reinterpret_cast<__half2*>(&r.x));
            float2 f1 = __half22float2(*reinterpret_cast<__half2*>(&r.y));
            float2 f2 = __half22float2(*reinterpret_cast<__half2*>(&r.z));
            float2 f3 = __half22float2(*reinterpret_cast<__half2*>(&r.w));
            ua[q] = make_float4(f0.x, f0.y, f1.x, f1.y);
            ub[q] = make_float4(f2.x, f2.y, f3.x, f3.y);
        }

        float t[4];
        #pragma unroll
        for (int q = 0; q < 4; q++) {
            float d = ua[q].x * vqa[q].x;
            d = fmaf(ua[q].y, vqa[q].y, d);
            d = fmaf(ua[q].z, vqa[q].z, d);
            d = fmaf(ua[q].w, vqa[q].w, d);
            d = fmaf(ub[q].x, vqb[q].x, d);
            d = fmaf(ub[q].y, vqb[q].y, d);
            d = fmaf(ub[q].z, vqb[q].z, d);
            d = fmaf(ub[q].w, vqb[q].w, d);
            d += __shfl_xor_sync(0xffffffffu, d, 1);  // partner half of d-range
            t[q] = d;                                 // logit[n], n=16q'+(l>>1)
        }

        // softmax over 64 n's: local over q', butterfly over (l>>1) groups
        float m = fmaxf(fmaxf(t[0], t[1]), fmaxf(t[2], t[3]));
        m = fmaxf(m, __shfl_xor_sync(0xffffffffu, m, 2));
        m = fmaxf(m, __shfl_xor_sync(0xffffffffu, m, 4));
        m = fmaxf(m, __shfl_xor_sync(0xffffffffu, m, 8));
        m = fmaxf(m, __shfl_xor_sync(0xffffffffu, m, 16));
        float Z = 0.f;
        #pragma unroll
        for (int q = 0; q < 4; q++) { t[q] = __expf(t[q] - m); Z += t[q]; }
        Z += __shfl_xor_sync(0xffffffffu, Z, 2);
        Z += __shfl_xor_sync(0xffffffffu, Z, 4);
        Z += __shfl_xor_sync(0xffffffffu, Z, 8);
        Z += __shfl_xor_sync(0xffffffffu, Z, 16);
        float inv = __fdividef(1.0f, Z);

        #pragma unroll
        for (int q = 0; q < 4; q++) {
            float c = t[q] * inv;
            sacca[q].x = fmaf(c, ua[q].x, sacca[q].x);
            sacca[q].y = fmaf(c, ua[q].y, sacca[q].y);
            sacca[q].z = fmaf(c, ua[q].z, sacca[q].z);
            sacca[q].w = fmaf(c, ua[q].w, sacca[q].w);
            saccb[q].x = fmaf(c, ub[q].x, saccb[q].x);
            saccb[q].y = fmaf(c, ub[q].y, saccb[q].y);
            saccb[q].z = fmaf(c, ub[q].z, saccb[q].z);
            saccb[q].w = fmaf(c, ub[q].w, saccb[q].w);
        }
    }

    // block-level reduction of s partials (8 warps -> 1), then plain store
    __shared__ float ss[8 * J];
    #pragma unroll
    for (int q = 0; q < 4; q++) {
        *(float4*)&ss[w * J + q * 256 + l * 8]     = sacca[q];
        *(float4*)&ss[w * J + q * 256 + l * 8 + 4] = saccb[q];
    }
    __syncthreads();

    int t4 = threadIdx.x;                           // one float4 per thread
    float4 tot = *(float4*)&ss[t4 * 4];
    #pragma unroll
    for (int ww = 1; ww < 8; ww++) {
        float4 p = *(float4*)&ss[ww * J + t4 * 4];
        tot.x += p.x; tot.y += p.y; tot.z += p.z; tot.w += p.w;
    }
    *(float4*)&g_spart[(b * NCH + ch) * J + t4 * 4] = tot;
}

// ---------------------------------------------------------------------------
extern "C" void kernel_launch(void* const* d_in, const int* in_sizes, int n_in,
                              void* d_out, int out_size)
{
    const float* x    = (const float*)d_in[0];
    const float* W    = (const float*)d_in[1];
    const float* bias = (const float*)d_in[2];
    float* out = (float*)d_out;

    proj_kernel<<<ICAPS, 256>>>(x, W);
    reduce0_kernel<<<dim3(B_, NCH), 256>>>();
    squash_kernel<0><<<256, 256>>>(bias, out);      // v0 ; vlogit = v0
    route_kernel<<<dim3(B_, NCH), 256>>>();         // logits u.v0 -> s1
    squash_kernel<1><<<256, 256>>>(bias, out);      // v1 ; vlogit = v0+v1
    route_kernel<<<dim3(B_, NCH), 256>>>();         // logits u.(v0+v1) -> s2
    squash_kernel<2><<<256, 256>>>(bias, out);      // v2 -> d_out
}